// round 1
// baseline (speedup 1.0000x reference)
#include <cuda_runtime.h>
#include <math.h>

// ---------------------------------------------------------------------------
// Problem constants
// ---------------------------------------------------------------------------
#define BATCH 32
#define SEQ   512
#define DMODEL 512
#define DTIME  256
#define NHEAD  8
#define HD     64
#define VD     32
#define DFF    2048
#define NROWS  (BATCH * SEQ)      // 16384
#define DCAT   (DMODEL + DTIME)   // 768
#define MTN    16

// ---------------------------------------------------------------------------
// Scratch (device globals; no runtime allocation)
// ---------------------------------------------------------------------------
__device__ float g_tmp [ (size_t)NROWS * DMODEL ];   // LN out / attn-proj
__device__ float g_xtok[ (size_t)NROWS * DMODEL ];
__device__ float g_xtim[ (size_t)NROWS * DTIME  ];
__device__ float g_qkv [ (size_t)NROWS * 3 * DMODEL ];
__device__ float g_attn[ (size_t)NROWS * DMODEL ];
__device__ float g_diag[ (size_t)NROWS * NHEAD  ];
__device__ float g_xc  [ (size_t)NROWS * DCAT   ];
__device__ float g_ff1 [ (size_t)NROWS * DFF    ];
__device__ float g_ff2 [ (size_t)NROWS * DCAT   ];
__device__ float g_pool[ (size_t)BATCH * (SEQ/MTN) * DCAT ];
__device__ float g_fin [ (size_t)BATCH * (SEQ/MTN) * DTIME ];

// ---------------------------------------------------------------------------
// Block reduction (blockDim.x == 256)
// ---------------------------------------------------------------------------
__device__ __forceinline__ float block_sum(float v) {
    __shared__ float sh[8];
    int lane = threadIdx.x & 31, w = threadIdx.x >> 5;
#pragma unroll
    for (int o = 16; o; o >>= 1) v += __shfl_xor_sync(0xffffffffu, v, o);
    if (lane == 0) sh[w] = v;
    __syncthreads();
    float t = 0.f;
#pragma unroll
    for (int i = 0; i < 8; ++i) t += sh[i];
    __syncthreads();
    return t;
}

// ---------------------------------------------------------------------------
// Generic LayerNorm: x = in[row]  (optionally *(1+diag_head), optionally +res)
// out = (x-mean)*rstd*g + b     one block per row, D <= 512
// ---------------------------------------------------------------------------
__global__ __launch_bounds__(256) void ln_kernel(
    const float* __restrict__ in, int istride,
    const float* __restrict__ res, int rstride,
    const float* __restrict__ diag,
    const float* __restrict__ g, const float* __restrict__ b,
    float* __restrict__ out, int ostride, int D)
{
    __shared__ float buf[512];
    const int row = blockIdx.x;
    const float* ip = in + (size_t)row * istride;

    float sum = 0.f;
    for (int c = threadIdx.x; c < D; c += 256) {
        float x = ip[c];
        if (diag) x *= 1.f + diag[(size_t)row * NHEAD + (c >> 5)];
        if (res)  x += res[(size_t)row * rstride + c];
        buf[c] = x;
        sum += x;
    }
    sum = block_sum(sum);
    const float mean = sum / D;

    float vs = 0.f;
    for (int c = threadIdx.x; c < D; c += 256) {
        float d = buf[c] - mean;
        vs += d * d;
    }
    vs = block_sum(vs);
    const float rstd = rsqrtf(vs / D + 1e-5f);

    for (int c = threadIdx.x; c < D; c += 256)
        out[(size_t)row * ostride + c] = (buf[c] - mean) * rstd * g[c] + b[c];
}

// ---------------------------------------------------------------------------
// fp32 NT GEMM:  C[n,m] = act( sum_k A[n,k]*W[m,k] + bias[m] )
// A:[N,K] row-major, W:[M,K] row-major.  128x128 tile, 256 thr, 8x8 micro.
// N,M multiples of 128; K multiple of 8.  act: 0 none, 1 relu, 2 exact gelu
// ---------------------------------------------------------------------------
__global__ __launch_bounds__(256) void gemm_nt(
    const float* __restrict__ A, const float* __restrict__ W,
    const float* __restrict__ bias, float* __restrict__ C,
    int N, int M, int K, int act)
{
    __shared__ float As[8][128];
    __shared__ float Bs[8][128];

    const int tid  = threadIdx.x;
    const int row0 = blockIdx.y * 128;
    const int col0 = blockIdx.x * 128;
    const int lr = tid >> 1;           // 0..127
    const int lk = (tid & 1) * 4;      // 0 or 4
    const int tr = tid >> 4;           // 0..15
    const int tc = tid & 15;           // 0..15

    float acc[8][8];
#pragma unroll
    for (int i = 0; i < 8; ++i)
#pragma unroll
        for (int j = 0; j < 8; ++j) acc[i][j] = 0.f;

    const float* Ap = A + (size_t)(row0 + lr) * K + lk;
    const float* Wp = W + (size_t)(col0 + lr) * K + lk;

    for (int k0 = 0; k0 < K; k0 += 8) {
        float4 a = *(const float4*)(Ap + k0);
        float4 w = *(const float4*)(Wp + k0);
        As[lk + 0][lr] = a.x; As[lk + 1][lr] = a.y;
        As[lk + 2][lr] = a.z; As[lk + 3][lr] = a.w;
        Bs[lk + 0][lr] = w.x; Bs[lk + 1][lr] = w.y;
        Bs[lk + 2][lr] = w.z; Bs[lk + 3][lr] = w.w;
        __syncthreads();

#pragma unroll
        for (int k = 0; k < 8; ++k) {
            float4 a0 = *(const float4*)&As[k][tr * 8];
            float4 a1 = *(const float4*)&As[k][tr * 8 + 4];
            float4 b0 = *(const float4*)&Bs[k][tc * 8];
            float4 b1 = *(const float4*)&Bs[k][tc * 8 + 4];
            float av[8] = {a0.x, a0.y, a0.z, a0.w, a1.x, a1.y, a1.z, a1.w};
            float bv[8] = {b0.x, b0.y, b0.z, b0.w, b1.x, b1.y, b1.z, b1.w};
#pragma unroll
            for (int i = 0; i < 8; ++i)
#pragma unroll
                for (int j = 0; j < 8; ++j)
                    acc[i][j] = fmaf(av[i], bv[j], acc[i][j]);
        }
        __syncthreads();
    }

    // epilogue
#pragma unroll
    for (int i = 0; i < 8; ++i) {
        const size_t r = (size_t)(row0 + tr * 8 + i);
        float* cp = C + r * M + col0 + tc * 8;
        float o[8];
#pragma unroll
        for (int j = 0; j < 8; ++j) {
            float v = acc[i][j] + bias[col0 + tc * 8 + j];
            if (act == 1)      v = fmaxf(v, 0.f);
            else if (act == 2) v = 0.5f * v * (1.f + erff(v * 0.70710678118654752f));
            o[j] = v;
        }
        *(float4*)cp       = make_float4(o[0], o[1], o[2], o[3]);
        *(float4*)(cp + 4) = make_float4(o[4], o[5], o[6], o[7]);
    }
}

// ---------------------------------------------------------------------------
// Flash attention (fp32) + diagonal-of-probs extraction.
// grid (L/64, H, B), 256 threads. Q tile 64x64 persistent in smem; K loaded
// transposed; V row-major (same buffer); P tile in smem; online softmax state
// in registers (replicated across the 16-lane row group).
// ---------------------------------------------------------------------------
__global__ __launch_bounds__(256) void attn_kernel(
    const float* __restrict__ qkv,
    float* __restrict__ attn_out,
    float* __restrict__ diag_out)
{
    __shared__ float Qs[64 * 64];
    __shared__ float KV[64 * 64];
    __shared__ float Ps[64 * 64];

    const int qt = blockIdx.x, h = blockIdx.y, b = blockIdx.z;
    const int tid = threadIdx.x;
    const int tr = tid >> 4, tc = tid & 15;
    const size_t rowbase = (size_t)b * SEQ;
    const int q0 = qt * 64;
    const int qoff = h * HD;

    // Load Q tile, pre-scaled by 1/sqrt(HD) = 0.125
    for (int i = tid; i < 1024; i += 256) {
        int r = i >> 4, c4 = (i & 15) << 2;
        float4 v = *(const float4*)(qkv + (rowbase + q0 + r) * 1536 + qoff + c4);
        Qs[r * 64 + c4 + 0] = v.x * 0.125f;
        Qs[r * 64 + c4 + 1] = v.y * 0.125f;
        Qs[r * 64 + c4 + 2] = v.z * 0.125f;
        Qs[r * 64 + c4 + 3] = v.w * 0.125f;
    }

    float m[4], l[4], du[4], acc[4][4];
#pragma unroll
    for (int i = 0; i < 4; ++i) {
        m[i] = -1e30f; l[i] = 0.f; du[i] = 0.f;
#pragma unroll
        for (int j = 0; j < 4; ++j) acc[i][j] = 0.f;
    }

    for (int kt = 0; kt < 8; ++kt) {
        const int kb = kt * 64;
        __syncthreads();   // previous PV reads of KV done (also covers Q load, iter 0)

        // K tile, transposed: KV[d*64 + r]
        for (int i = tid; i < 1024; i += 256) {
            int r = i >> 4, c4 = (i & 15) << 2;
            float4 v = *(const float4*)(qkv + (rowbase + kb + r) * 1536 + 512 + qoff + c4);
            KV[(c4 + 0) * 64 + r] = v.x;
            KV[(c4 + 1) * 64 + r] = v.y;
            KV[(c4 + 2) * 64 + r] = v.z;
            KV[(c4 + 3) * 64 + r] = v.w;
        }
        __syncthreads();

        // S = Q * K^T  (4x4 per thread)
        float s[4][4];
#pragma unroll
        for (int i = 0; i < 4; ++i)
#pragma unroll
            for (int j = 0; j < 4; ++j) s[i][j] = 0.f;

        for (int d0 = 0; d0 < 64; d0 += 4) {
            float qa[4][4];
#pragma unroll
            for (int i = 0; i < 4; ++i) {
                float4 q = *(const float4*)&Qs[(tr * 4 + i) * 64 + d0];
                qa[i][0] = q.x; qa[i][1] = q.y; qa[i][2] = q.z; qa[i][3] = q.w;
            }
#pragma unroll
            for (int dd = 0; dd < 4; ++dd) {
                float4 kf = *(const float4*)&KV[(d0 + dd) * 64 + tc * 4];
#pragma unroll
                for (int i = 0; i < 4; ++i) {
                    s[i][0] = fmaf(qa[i][dd], kf.x, s[i][0]);
                    s[i][1] = fmaf(qa[i][dd], kf.y, s[i][1]);
                    s[i][2] = fmaf(qa[i][dd], kf.z, s[i][2]);
                    s[i][3] = fmaf(qa[i][dd], kf.w, s[i][3]);
                }
            }
        }

        // Online softmax per row (16-lane group == half warp)
#pragma unroll
        for (int i = 0; i < 4; ++i) {
            float tm = fmaxf(fmaxf(s[i][0], s[i][1]), fmaxf(s[i][2], s[i][3]));
#pragma unroll
            for (int o = 8; o; o >>= 1)
                tm = fmaxf(tm, __shfl_xor_sync(0xffffffffu, tm, o));
            float mn = fmaxf(m[i], tm);
            float cf = expf(m[i] - mn);
            float rs = 0.f;
#pragma unroll
            for (int j = 0; j < 4; ++j) {
                float p = expf(s[i][j] - mn);
                s[i][j] = p;
                rs += p;
            }
#pragma unroll
            for (int o = 8; o; o >>= 1)
                rs += __shfl_xor_sync(0xffffffffu, rs, o);
            l[i] = l[i] * cf + rs;
            du[i] *= cf;
#pragma unroll
            for (int j = 0; j < 4; ++j) acc[i][j] *= cf;
            m[i] = mn;

            const int gr = q0 + tr * 4 + i;           // global q row (local in seq)
            if (gr >= kb && gr < kb + 64) {
                int lc = gr - kb;
                if ((lc >> 2) == tc) du[i] += s[i][lc & 3];
            }
            *(float4*)&Ps[(tr * 4 + i) * 64 + tc * 4] =
                make_float4(s[i][0], s[i][1], s[i][2], s[i][3]);
        }
        __syncthreads();   // all S reads of KV done, Ps complete

        // V tile, row-major: KV[r*64 + d]
        for (int i = tid; i < 1024; i += 256) {
            int r = i >> 4, c4 = (i & 15) << 2;
            float4 v = *(const float4*)(qkv + (rowbase + kb + r) * 1536 + 1024 + qoff + c4);
            KV[r * 64 + c4 + 0] = v.x;
            KV[r * 64 + c4 + 1] = v.y;
            KV[r * 64 + c4 + 2] = v.z;
            KV[r * 64 + c4 + 3] = v.w;
        }
        __syncthreads();

        // O += P * V
        for (int k0 = 0; k0 < 64; k0 += 4) {
            float pa[4][4];
#pragma unroll
            for (int i = 0; i < 4; ++i) {
                float4 p = *(const float4*)&Ps[(tr * 4 + i) * 64 + k0];
                pa[i][0] = p.x; pa[i][1] = p.y; pa[i][2] = p.z; pa[i][3] = p.w;
            }
#pragma unroll
            for (int kk = 0; kk < 4; ++kk) {
                float4 vf = *(const float4*)&KV[(k0 + kk) * 64 + tc * 4];
#pragma unroll
                for (int i = 0; i < 4; ++i) {
                    acc[i][0] = fmaf(pa[i][kk], vf.x, acc[i][0]);
                    acc[i][1] = fmaf(pa[i][kk], vf.y, acc[i][1]);
                    acc[i][2] = fmaf(pa[i][kk], vf.z, acc[i][2]);
                    acc[i][3] = fmaf(pa[i][kk], vf.w, acc[i][3]);
                }
            }
        }
    }

    // Epilogue: normalize, write O and diag
#pragma unroll
    for (int i = 0; i < 4; ++i) {
        const float inv = 1.f / l[i];
        const size_t r = rowbase + q0 + tr * 4 + i;
        *(float4*)(attn_out + r * DMODEL + qoff + tc * 4) =
            make_float4(acc[i][0] * inv, acc[i][1] * inv,
                        acc[i][2] * inv, acc[i][3] * inv);
        float ds = du[i] * inv;
#pragma unroll
        for (int o = 8; o; o >>= 1)
            ds += __shfl_xor_sync(0xffffffffu, ds, o);
        if (tc == 0) diag_out[r * NHEAD + h] = ds;
    }
}

// ---------------------------------------------------------------------------
// MaxPool over seq (k=stride=16) producing concatenated [B,32,768]
// ---------------------------------------------------------------------------
__global__ __launch_bounds__(256) void pool_kernel(
    const float* __restrict__ xtok, const float* __restrict__ xtim,
    float* __restrict__ pool)
{
    const int bidx = blockIdx.x;                 // 0..1023
    const int b = bidx >> 5, ch = bidx & 31;
    const size_t r0 = (size_t)b * SEQ + ch * MTN;
    for (int c = threadIdx.x; c < DCAT; c += 256) {
        float mx = -1e30f;
        if (c < DMODEL) {
            const float* p = xtok + r0 * DMODEL + c;
#pragma unroll
            for (int t = 0; t < MTN; ++t) mx = fmaxf(mx, p[(size_t)t * DMODEL]);
        } else {
            const float* p = xtim + r0 * DTIME + (c - DMODEL);
#pragma unroll
            for (int t = 0; t < MTN; ++t) mx = fmaxf(mx, p[(size_t)t * DTIME]);
        }
        pool[(size_t)bidx * DCAT + c] = mx;
    }
}

// ---------------------------------------------------------------------------
// Host driver
// ---------------------------------------------------------------------------
extern "C" void kernel_launch(void* const* d_in, const int* in_sizes, int n_in,
                              void* d_out, int out_size)
{
    const float* src_token = (const float*)d_in[0];
    const float* src_time  = (const float*)d_in[1];
    const float* norm0_g   = (const float*)d_in[2];
    const float* norm0_b   = (const float*)d_in[3];
    const float* in_w      = (const float*)d_in[4];
    const float* in_b      = (const float*)d_in[5];
    const float* qkv_w     = (const float*)d_in[6];
    const float* qkv_b     = (const float*)d_in[7];
    const float* ao_w      = (const float*)d_in[8];
    const float* ao_b      = (const float*)d_in[9];
    const float* lin1_w    = (const float*)d_in[10];
    const float* lin1_b    = (const float*)d_in[11];
    const float* lin2_w    = (const float*)d_in[12];
    const float* lin2_b    = (const float*)d_in[13];
    const float* n1_g = (const float*)d_in[14];
    const float* n1_b = (const float*)d_in[15];
    const float* n2_g = (const float*)d_in[16];
    const float* n2_b = (const float*)d_in[17];
    const float* n3_g = (const float*)d_in[18];
    const float* n3_b = (const float*)d_in[19];
    const float* n4_g = (const float*)d_in[20];
    const float* n4_b = (const float*)d_in[21];
    const float* out_w = (const float*)d_in[22];
    const float* out_b = (const float*)d_in[23];
    const float* ln_g  = (const float*)d_in[24];
    const float* ln_b  = (const float*)d_in[25];
    float* outp = (float*)d_out;

    float *tmp, *xtok, *xtim, *qkv, *attn, *diag, *xc, *ff1, *ff2, *pool, *fin;
    cudaGetSymbolAddress((void**)&tmp,  g_tmp);
    cudaGetSymbolAddress((void**)&xtok, g_xtok);
    cudaGetSymbolAddress((void**)&xtim, g_xtim);
    cudaGetSymbolAddress((void**)&qkv,  g_qkv);
    cudaGetSymbolAddress((void**)&attn, g_attn);
    cudaGetSymbolAddress((void**)&diag, g_diag);
    cudaGetSymbolAddress((void**)&xc,   g_xc);
    cudaGetSymbolAddress((void**)&ff1,  g_ff1);
    cudaGetSymbolAddress((void**)&ff2,  g_ff2);
    cudaGetSymbolAddress((void**)&pool, g_pool);
    cudaGetSymbolAddress((void**)&fin,  g_fin);

    const float* xtok_in = src_token;
    const float* xtim_in = src_time;

    for (int i = 0; i < 2; ++i) {
        const float* n0g = norm0_g + i * 512;
        const float* n0b = norm0_b + i * 512;
        const float* iw  = in_w  + (size_t)i * 512 * 512;
        const float* ib  = in_b  + i * 512;
        const float* qw  = qkv_w + (size_t)i * 1536 * 512;
        const float* qb  = qkv_b + i * 1536;
        const float* aw  = ao_w  + (size_t)i * 512 * 512;
        const float* ab  = ao_b  + i * 512;
        const float* l1w = lin1_w + (size_t)i * 2048 * 768;
        const float* l1b = lin1_b + i * 2048;
        const float* l2w = lin2_w + (size_t)i * 768 * 2048;
        const float* l2b = lin2_b + i * 768;

        // 1. norm0 LN
        ln_kernel<<<NROWS, 256>>>(xtok_in, 512, nullptr, 0, nullptr,
                                  n0g, n0b, tmp, 512, 512);
        // 2. in_proj
        gemm_nt<<<dim3(4, 128), 256>>>(tmp, iw, ib, xtok, NROWS, 512, 512, 0);
        // 3. qkv
        gemm_nt<<<dim3(12, 128), 256>>>(xtok, qw, qb, qkv, NROWS, 1536, 512, 0);
        // 4. attention + diag
        attn_kernel<<<dim3(8, 8, 32), 256>>>(qkv, attn, diag);
        // 5. attn output proj
        gemm_nt<<<dim3(4, 128), 256>>>(attn, aw, ab, tmp, NROWS, 512, 512, 0);
        // 6. n1: LN(attn_proj + xtok) -> xc[:, :512]
        ln_kernel<<<NROWS, 256>>>(tmp, 512, xtok, 512, nullptr,
                                  n1_g + i * 512, n1_b + i * 512, xc, 768, 512);
        // 7. n2: LN(x_time*(1+diag)) -> xc[:, 512:]
        ln_kernel<<<NROWS, 256>>>(xtim_in, 256, nullptr, 0, diag,
                                  n2_g + i * 256, n2_b + i * 256, xc + 512, 768, 256);
        // 8. lin1 + relu
        gemm_nt<<<dim3(16, 128), 256>>>(xc, l1w, l1b, ff1, NROWS, 2048, 768, 1);
        // 9. lin2
        gemm_nt<<<dim3(6, 128), 256>>>(ff1, l2w, l2b, ff2, NROWS, 768, 2048, 0);
        // 10. n3: LN(ff[:, :512] + xc_tok) -> xtok
        ln_kernel<<<NROWS, 256>>>(ff2, 768, xc, 768, nullptr,
                                  n3_g + i * 512, n3_b + i * 512, xtok, 512, 512);
        // 11. n4: LN(ff[:, 512:] + xc_time) -> xtim
        ln_kernel<<<NROWS, 256>>>(ff2 + 512, 768, xc + 512, 768, nullptr,
                                  n4_g + i * 256, n4_b + i * 256, xtim, 256, 256);

        xtok_in = xtok;
        xtim_in = xtim;
    }

    // pool + output head
    pool_kernel<<<1024, 256>>>(xtok, xtim, pool);
    gemm_nt<<<dim3(2, 8), 256>>>(pool, out_w, out_b, fin, 1024, 256, 768, 2);
    ln_kernel<<<1024, 256>>>(fin, 256, nullptr, 0, nullptr, ln_g, ln_b,
                             outp, 256, 256);
}

// round 2
// speedup vs baseline: 2.0470x; 2.0470x over previous
#include <cuda_runtime.h>
#include <math.h>

// ---------------------------------------------------------------------------
// Problem constants
// ---------------------------------------------------------------------------
#define BATCH 32
#define SEQ   512
#define DMODEL 512
#define DTIME  256
#define NHEAD  8
#define HD     64
#define VD     32
#define DFF    2048
#define NROWS  (BATCH * SEQ)      // 16384
#define DCAT   (DMODEL + DTIME)   // 768
#define MTN    16

// ---------------------------------------------------------------------------
// Scratch (device globals; no runtime allocation)
// ---------------------------------------------------------------------------
__device__ float g_tmp [ (size_t)NROWS * DMODEL ];
__device__ float g_xtok[ (size_t)NROWS * DMODEL ];
__device__ float g_xtim[ (size_t)NROWS * DTIME  ];
__device__ float g_qkv [ (size_t)NROWS * 3 * DMODEL ];
__device__ float g_attn[ (size_t)NROWS * DMODEL ];
__device__ float g_diag[ (size_t)NROWS * NHEAD  ];
__device__ float g_xc  [ (size_t)NROWS * DCAT   ];
__device__ float g_ff1 [ (size_t)NROWS * DFF    ];
__device__ float g_ff2 [ (size_t)NROWS * DCAT   ];
__device__ float g_pool[ (size_t)BATCH * (SEQ/MTN) * DCAT ];
__device__ float g_fin [ (size_t)BATCH * (SEQ/MTN) * DTIME ];

// ---------------------------------------------------------------------------
// Helpers
// ---------------------------------------------------------------------------
__device__ __forceinline__ float f2tf(float x) {
    unsigned r;
    asm("cvt.rna.tf32.f32 %0, %1;" : "=r"(r) : "f"(x));
    return __uint_as_float(r);
}

__device__ __forceinline__ void mma_tf32(float* d, const float* a, const float* b) {
    asm volatile(
        "mma.sync.aligned.m16n8k8.row.col.f32.tf32.tf32.f32 "
        "{%0,%1,%2,%3},{%4,%5,%6,%7},{%8,%9},{%0,%1,%2,%3};\n"
        : "+f"(d[0]), "+f"(d[1]), "+f"(d[2]), "+f"(d[3])
        : "r"(__float_as_uint(a[0])), "r"(__float_as_uint(a[1])),
          "r"(__float_as_uint(a[2])), "r"(__float_as_uint(a[3])),
          "r"(__float_as_uint(b[0])), "r"(__float_as_uint(b[1])));
}

__device__ __forceinline__ float block_sum(float v) {
    __shared__ float sh[8];
    int lane = threadIdx.x & 31, w = threadIdx.x >> 5;
#pragma unroll
    for (int o = 16; o; o >>= 1) v += __shfl_xor_sync(0xffffffffu, v, o);
    if (lane == 0) sh[w] = v;
    __syncthreads();
    float t = 0.f;
#pragma unroll
    for (int i = 0; i < 8; ++i) t += sh[i];
    __syncthreads();
    return t;
}

// ---------------------------------------------------------------------------
// Generic LayerNorm (optionally *(1+diag_head), optionally +res)
// ---------------------------------------------------------------------------
__global__ __launch_bounds__(256) void ln_kernel(
    const float* __restrict__ in, int istride,
    const float* __restrict__ res, int rstride,
    const float* __restrict__ diag,
    const float* __restrict__ g, const float* __restrict__ b,
    float* __restrict__ out, int ostride, int D)
{
    __shared__ float buf[512];
    const int row = blockIdx.x;
    const float* ip = in + (size_t)row * istride;

    float sum = 0.f;
    for (int c = threadIdx.x; c < D; c += 256) {
        float x = ip[c];
        if (diag) x *= 1.f + diag[(size_t)row * NHEAD + (c >> 5)];
        if (res)  x += res[(size_t)row * rstride + c];
        buf[c] = x;
        sum += x;
    }
    sum = block_sum(sum);
    const float mean = sum / D;

    float vs = 0.f;
    for (int c = threadIdx.x; c < D; c += 256) {
        float d = buf[c] - mean;
        vs += d * d;
    }
    vs = block_sum(vs);
    const float rstd = rsqrtf(vs / D + 1e-5f);

    for (int c = threadIdx.x; c < D; c += 256)
        out[(size_t)row * ostride + c] = (buf[c] - mean) * rstd * g[c] + b[c];
}

// ---------------------------------------------------------------------------
// tf32 tensor-core NT GEMM: C[n,m] = act( sum_k A[n,k]*W[m,k] + bias[m] )
// 128x128 block tile, 8 warps (2x4), 64x32 warp tile, K-step 16, dbl-buffered.
// smem k-cols permuted in pairs (k, k+4)->(2k%8, 2k%8+1) so each mma fragment
// load is a single LDS.64; row stride 24 floats -> conflict-free.
// N,M multiples of 128 (M also 256 ok via grid); K multiple of 16.
// act: 0 none, 1 relu, 2 exact gelu
// ---------------------------------------------------------------------------
__global__ __launch_bounds__(256) void gemm_tf32(
    const float* __restrict__ A, const float* __restrict__ W,
    const float* __restrict__ bias, float* __restrict__ C,
    int N, int M, int K, int act)
{
    __shared__ float As[2][128][24];
    __shared__ float Bs[2][128][24];

    const int tid  = threadIdx.x;
    const int lane = tid & 31;
    const int warp = tid >> 5;
    const int wm = (warp & 1) * 64;       // warp m-offset
    const int wn = (warp >> 1) * 32;      // warp n-offset
    const int r4 = lane >> 2;             // 0..7
    const int c2 = (lane & 3) * 2;        // permuted k-pair offset

    const int row0 = blockIdx.y * 128;
    const int col0 = blockIdx.x * 128;

    const int lrow = tid >> 1;            // 0..127
    const int lk   = (tid & 1) * 8;       // 0 or 8

    const float* Ap = A + (size_t)(row0 + lrow) * K + lk;
    const float* Wp = W + (size_t)(col0 + lrow) * K + lk;

    float acc[4][4][4];
#pragma unroll
    for (int i = 0; i < 4; ++i)
#pragma unroll
        for (int j = 0; j < 4; ++j)
#pragma unroll
            for (int q = 0; q < 4; ++q) acc[i][j][q] = 0.f;

    float4 ra0, ra1, rb0, rb1;

#define LOAD_TILE(kt)                                            \
    do {                                                         \
        const int k0_ = (kt) * 16;                               \
        ra0 = *(const float4*)(Ap + k0_);                        \
        ra1 = *(const float4*)(Ap + k0_ + 4);                    \
        rb0 = *(const float4*)(Wp + k0_);                        \
        rb1 = *(const float4*)(Wp + k0_ + 4);                    \
    } while (0)

#define STORE_TILE(bb)                                                        \
    do {                                                                      \
        float* da = &As[bb][lrow][lk];                                        \
        float* db = &Bs[bb][lrow][lk];                                        \
        ((float2*)da)[0] = make_float2(f2tf(ra0.x), f2tf(ra1.x));             \
        ((float2*)da)[1] = make_float2(f2tf(ra0.y), f2tf(ra1.y));             \
        ((float2*)da)[2] = make_float2(f2tf(ra0.z), f2tf(ra1.z));             \
        ((float2*)da)[3] = make_float2(f2tf(ra0.w), f2tf(ra1.w));             \
        ((float2*)db)[0] = make_float2(f2tf(rb0.x), f2tf(rb1.x));             \
        ((float2*)db)[1] = make_float2(f2tf(rb0.y), f2tf(rb1.y));             \
        ((float2*)db)[2] = make_float2(f2tf(rb0.z), f2tf(rb1.z));             \
        ((float2*)db)[3] = make_float2(f2tf(rb0.w), f2tf(rb1.w));             \
    } while (0)

    const int NT = K >> 4;
    LOAD_TILE(0);
    STORE_TILE(0);
    __syncthreads();

    for (int kt = 0; kt < NT; ++kt) {
        const int buf = kt & 1;
        if (kt + 1 < NT) LOAD_TILE(kt + 1);

#pragma unroll
        for (int s = 0; s < 2; ++s) {
            const int ko = s * 8;
            float a[4][4], b[4][2];
#pragma unroll
            for (int mt = 0; mt < 4; ++mt) {
                float2 t0 = *(const float2*)&As[buf][wm + mt * 16 + r4][ko + c2];
                float2 t1 = *(const float2*)&As[buf][wm + mt * 16 + 8 + r4][ko + c2];
                a[mt][0] = t0.x; a[mt][1] = t1.x; a[mt][2] = t0.y; a[mt][3] = t1.y;
            }
#pragma unroll
            for (int nt = 0; nt < 4; ++nt) {
                float2 tb = *(const float2*)&Bs[buf][wn + nt * 8 + r4][ko + c2];
                b[nt][0] = tb.x; b[nt][1] = tb.y;
            }
#pragma unroll
            for (int mt = 0; mt < 4; ++mt)
#pragma unroll
                for (int nt = 0; nt < 4; ++nt)
                    mma_tf32(acc[mt][nt], a[mt], b[nt]);
        }

        if (kt + 1 < NT) {
            STORE_TILE(buf ^ 1);
            __syncthreads();
        }
    }
#undef LOAD_TILE
#undef STORE_TILE

    // epilogue
#pragma unroll
    for (int mt = 0; mt < 4; ++mt) {
        const int row = row0 + wm + mt * 16 + r4;
#pragma unroll
        for (int nt = 0; nt < 4; ++nt) {
            const int col = col0 + wn + nt * 8 + c2;
            const float b0 = bias[col], b1 = bias[col + 1];
            float v[4];
            v[0] = acc[mt][nt][0] + b0;
            v[1] = acc[mt][nt][1] + b1;
            v[2] = acc[mt][nt][2] + b0;
            v[3] = acc[mt][nt][3] + b1;
            if (act == 1) {
#pragma unroll
                for (int q = 0; q < 4; ++q) v[q] = fmaxf(v[q], 0.f);
            } else if (act == 2) {
#pragma unroll
                for (int q = 0; q < 4; ++q)
                    v[q] = 0.5f * v[q] * (1.f + erff(v[q] * 0.70710678118654752f));
            }
            *(float2*)&C[(size_t)row * M + col]       = make_float2(v[0], v[1]);
            *(float2*)&C[(size_t)(row + 8) * M + col] = make_float2(v[2], v[3]);
        }
    }
}

// ---------------------------------------------------------------------------
// Flash attention (fp32) + diagonal-of-probs extraction.
// ---------------------------------------------------------------------------
__global__ __launch_bounds__(256) void attn_kernel(
    const float* __restrict__ qkv,
    float* __restrict__ attn_out,
    float* __restrict__ diag_out)
{
    __shared__ float Qs[64 * 64];
    __shared__ float KV[64 * 64];
    __shared__ float Ps[64 * 64];

    const int qt = blockIdx.x, h = blockIdx.y, b = blockIdx.z;
    const int tid = threadIdx.x;
    const int tr = tid >> 4, tc = tid & 15;
    const size_t rowbase = (size_t)b * SEQ;
    const int q0 = qt * 64;
    const int qoff = h * HD;

    for (int i = tid; i < 1024; i += 256) {
        int r = i >> 4, c4 = (i & 15) << 2;
        float4 v = *(const float4*)(qkv + (rowbase + q0 + r) * 1536 + qoff + c4);
        Qs[r * 64 + c4 + 0] = v.x * 0.125f;
        Qs[r * 64 + c4 + 1] = v.y * 0.125f;
        Qs[r * 64 + c4 + 2] = v.z * 0.125f;
        Qs[r * 64 + c4 + 3] = v.w * 0.125f;
    }

    float m[4], l[4], du[4], acc[4][4];
#pragma unroll
    for (int i = 0; i < 4; ++i) {
        m[i] = -1e30f; l[i] = 0.f; du[i] = 0.f;
#pragma unroll
        for (int j = 0; j < 4; ++j) acc[i][j] = 0.f;
    }

    for (int kt = 0; kt < 8; ++kt) {
        const int kb = kt * 64;
        __syncthreads();

        for (int i = tid; i < 1024; i += 256) {
            int r = i >> 4, c4 = (i & 15) << 2;
            float4 v = *(const float4*)(qkv + (rowbase + kb + r) * 1536 + 512 + qoff + c4);
            KV[(c4 + 0) * 64 + r] = v.x;
            KV[(c4 + 1) * 64 + r] = v.y;
            KV[(c4 + 2) * 64 + r] = v.z;
            KV[(c4 + 3) * 64 + r] = v.w;
        }
        __syncthreads();

        float s[4][4];
#pragma unroll
        for (int i = 0; i < 4; ++i)
#pragma unroll
            for (int j = 0; j < 4; ++j) s[i][j] = 0.f;

        for (int d0 = 0; d0 < 64; d0 += 4) {
            float qa[4][4];
#pragma unroll
            for (int i = 0; i < 4; ++i) {
                float4 q = *(const float4*)&Qs[(tr * 4 + i) * 64 + d0];
                qa[i][0] = q.x; qa[i][1] = q.y; qa[i][2] = q.z; qa[i][3] = q.w;
            }
#pragma unroll
            for (int dd = 0; dd < 4; ++dd) {
                float4 kf = *(const float4*)&KV[(d0 + dd) * 64 + tc * 4];
#pragma unroll
                for (int i = 0; i < 4; ++i) {
                    s[i][0] = fmaf(qa[i][dd], kf.x, s[i][0]);
                    s[i][1] = fmaf(qa[i][dd], kf.y, s[i][1]);
                    s[i][2] = fmaf(qa[i][dd], kf.z, s[i][2]);
                    s[i][3] = fmaf(qa[i][dd], kf.w, s[i][3]);
                }
            }
        }

#pragma unroll
        for (int i = 0; i < 4; ++i) {
            float tm = fmaxf(fmaxf(s[i][0], s[i][1]), fmaxf(s[i][2], s[i][3]));
#pragma unroll
            for (int o = 8; o; o >>= 1)
                tm = fmaxf(tm, __shfl_xor_sync(0xffffffffu, tm, o));
            float mn = fmaxf(m[i], tm);
            float cf = expf(m[i] - mn);
            float rs = 0.f;
#pragma unroll
            for (int j = 0; j < 4; ++j) {
                float p = expf(s[i][j] - mn);
                s[i][j] = p;
                rs += p;
            }
#pragma unroll
            for (int o = 8; o; o >>= 1)
                rs += __shfl_xor_sync(0xffffffffu, rs, o);
            l[i] = l[i] * cf + rs;
            du[i] *= cf;
#pragma unroll
            for (int j = 0; j < 4; ++j) acc[i][j] *= cf;
            m[i] = mn;

            const int gr = q0 + tr * 4 + i;
            if (gr >= kb && gr < kb + 64) {
                int lc = gr - kb;
                if ((lc >> 2) == tc) du[i] += s[i][lc & 3];
            }
            *(float4*)&Ps[(tr * 4 + i) * 64 + tc * 4] =
                make_float4(s[i][0], s[i][1], s[i][2], s[i][3]);
        }
        __syncthreads();

        for (int i = tid; i < 1024; i += 256) {
            int r = i >> 4, c4 = (i & 15) << 2;
            float4 v = *(const float4*)(qkv + (rowbase + kb + r) * 1536 + 1024 + qoff + c4);
            KV[r * 64 + c4 + 0] = v.x;
            KV[r * 64 + c4 + 1] = v.y;
            KV[r * 64 + c4 + 2] = v.z;
            KV[r * 64 + c4 + 3] = v.w;
        }
        __syncthreads();

        for (int k0 = 0; k0 < 64; k0 += 4) {
            float pa[4][4];
#pragma unroll
            for (int i = 0; i < 4; ++i) {
                float4 p = *(const float4*)&Ps[(tr * 4 + i) * 64 + k0];
                pa[i][0] = p.x; pa[i][1] = p.y; pa[i][2] = p.z; pa[i][3] = p.w;
            }
#pragma unroll
            for (int kk = 0; kk < 4; ++kk) {
                float4 vf = *(const float4*)&KV[(k0 + kk) * 64 + tc * 4];
#pragma unroll
                for (int i = 0; i < 4; ++i) {
                    acc[i][0] = fmaf(pa[i][kk], vf.x, acc[i][0]);
                    acc[i][1] = fmaf(pa[i][kk], vf.y, acc[i][1]);
                    acc[i][2] = fmaf(pa[i][kk], vf.z, acc[i][2]);
                    acc[i][3] = fmaf(pa[i][kk], vf.w, acc[i][3]);
                }
            }
        }
    }

#pragma unroll
    for (int i = 0; i < 4; ++i) {
        const float inv = 1.f / l[i];
        const size_t r = rowbase + q0 + tr * 4 + i;
        *(float4*)(attn_out + r * DMODEL + qoff + tc * 4) =
            make_float4(acc[i][0] * inv, acc[i][1] * inv,
                        acc[i][2] * inv, acc[i][3] * inv);
        float ds = du[i] * inv;
#pragma unroll
        for (int o = 8; o; o >>= 1)
            ds += __shfl_xor_sync(0xffffffffu, ds, o);
        if (tc == 0) diag_out[r * NHEAD + h] = ds;
    }
}

// ---------------------------------------------------------------------------
// MaxPool over seq (k=stride=16) producing concatenated [B,32,768]
// ---------------------------------------------------------------------------
__global__ __launch_bounds__(256) void pool_kernel(
    const float* __restrict__ xtok, const float* __restrict__ xtim,
    float* __restrict__ pool)
{
    const int bidx = blockIdx.x;
    const int b = bidx >> 5, ch = bidx & 31;
    const size_t r0 = (size_t)b * SEQ + ch * MTN;
    for (int c = threadIdx.x; c < DCAT; c += 256) {
        float mx = -1e30f;
        if (c < DMODEL) {
            const float* p = xtok + r0 * DMODEL + c;
#pragma unroll
            for (int t = 0; t < MTN; ++t) mx = fmaxf(mx, p[(size_t)t * DMODEL]);
        } else {
            const float* p = xtim + r0 * DTIME + (c - DMODEL);
#pragma unroll
            for (int t = 0; t < MTN; ++t) mx = fmaxf(mx, p[(size_t)t * DTIME]);
        }
        pool[(size_t)bidx * DCAT + c] = mx;
    }
}

// ---------------------------------------------------------------------------
// Host driver
// ---------------------------------------------------------------------------
extern "C" void kernel_launch(void* const* d_in, const int* in_sizes, int n_in,
                              void* d_out, int out_size)
{
    const float* src_token = (const float*)d_in[0];
    const float* src_time  = (const float*)d_in[1];
    const float* norm0_g   = (const float*)d_in[2];
    const float* norm0_b   = (const float*)d_in[3];
    const float* in_w      = (const float*)d_in[4];
    const float* in_b      = (const float*)d_in[5];
    const float* qkv_w     = (const float*)d_in[6];
    const float* qkv_b     = (const float*)d_in[7];
    const float* ao_w      = (const float*)d_in[8];
    const float* ao_b      = (const float*)d_in[9];
    const float* lin1_w    = (const float*)d_in[10];
    const float* lin1_b    = (const float*)d_in[11];
    const float* lin2_w    = (const float*)d_in[12];
    const float* lin2_b    = (const float*)d_in[13];
    const float* n1_g = (const float*)d_in[14];
    const float* n1_b = (const float*)d_in[15];
    const float* n2_g = (const float*)d_in[16];
    const float* n2_b = (const float*)d_in[17];
    const float* n3_g = (const float*)d_in[18];
    const float* n3_b = (const float*)d_in[19];
    const float* n4_g = (const float*)d_in[20];
    const float* n4_b = (const float*)d_in[21];
    const float* out_w = (const float*)d_in[22];
    const float* out_b = (const float*)d_in[23];
    const float* ln_g  = (const float*)d_in[24];
    const float* ln_b  = (const float*)d_in[25];
    float* outp = (float*)d_out;

    float *tmp, *xtok, *xtim, *qkv, *attn, *diag, *xc, *ff1, *ff2, *pool, *fin;
    cudaGetSymbolAddress((void**)&tmp,  g_tmp);
    cudaGetSymbolAddress((void**)&xtok, g_xtok);
    cudaGetSymbolAddress((void**)&xtim, g_xtim);
    cudaGetSymbolAddress((void**)&qkv,  g_qkv);
    cudaGetSymbolAddress((void**)&attn, g_attn);
    cudaGetSymbolAddress((void**)&diag, g_diag);
    cudaGetSymbolAddress((void**)&xc,   g_xc);
    cudaGetSymbolAddress((void**)&ff1,  g_ff1);
    cudaGetSymbolAddress((void**)&ff2,  g_ff2);
    cudaGetSymbolAddress((void**)&pool, g_pool);
    cudaGetSymbolAddress((void**)&fin,  g_fin);

    const float* xtok_in = src_token;
    const float* xtim_in = src_time;

    for (int i = 0; i < 2; ++i) {
        const float* n0g = norm0_g + i * 512;
        const float* n0b = norm0_b + i * 512;
        const float* iw  = in_w  + (size_t)i * 512 * 512;
        const float* ib  = in_b  + i * 512;
        const float* qw  = qkv_w + (size_t)i * 1536 * 512;
        const float* qb  = qkv_b + i * 1536;
        const float* aw  = ao_w  + (size_t)i * 512 * 512;
        const float* ab  = ao_b  + i * 512;
        const float* l1w = lin1_w + (size_t)i * 2048 * 768;
        const float* l1b = lin1_b + i * 2048;
        const float* l2w = lin2_w + (size_t)i * 768 * 2048;
        const float* l2b = lin2_b + i * 768;

        ln_kernel<<<NROWS, 256>>>(xtok_in, 512, nullptr, 0, nullptr,
                                  n0g, n0b, tmp, 512, 512);
        gemm_tf32<<<dim3(4, 128), 256>>>(tmp, iw, ib, xtok, NROWS, 512, 512, 0);
        gemm_tf32<<<dim3(12, 128), 256>>>(xtok, qw, qb, qkv, NROWS, 1536, 512, 0);
        attn_kernel<<<dim3(8, 8, 32), 256>>>(qkv, attn, diag);
        gemm_tf32<<<dim3(4, 128), 256>>>(attn, aw, ab, tmp, NROWS, 512, 512, 0);
        ln_kernel<<<NROWS, 256>>>(tmp, 512, xtok, 512, nullptr,
                                  n1_g + i * 512, n1_b + i * 512, xc, 768, 512);
        ln_kernel<<<NROWS, 256>>>(xtim_in, 256, nullptr, 0, diag,
                                  n2_g + i * 256, n2_b + i * 256, xc + 512, 768, 256);
        gemm_tf32<<<dim3(16, 128), 256>>>(xc, l1w, l1b, ff1, NROWS, 2048, 768, 1);
        gemm_tf32<<<dim3(6, 128), 256>>>(ff1, l2w, l2b, ff2, NROWS, 768, 2048, 0);
        ln_kernel<<<NROWS, 256>>>(ff2, 768, xc, 768, nullptr,
                                  n3_g + i * 512, n3_b + i * 512, xtok, 512, 512);
        ln_kernel<<<NROWS, 256>>>(ff2 + 512, 768, xc + 512, 768, nullptr,
                                  n4_g + i * 256, n4_b + i * 256, xtim, 256, 256);

        xtok_in = xtok;
        xtim_in = xtim;
    }

    pool_kernel<<<1024, 256>>>(xtok, xtim, pool);
    gemm_tf32<<<dim3(2, 8), 256>>>(pool, out_w, out_b, fin, 1024, 256, 768, 2);
    ln_kernel<<<1024, 256>>>(fin, 256, nullptr, 0, nullptr, ln_g, ln_b,
                             outp, 256, 256);
}

// round 3
// speedup vs baseline: 2.4517x; 1.1977x over previous
#include <cuda_runtime.h>
#include <math.h>

// ---------------------------------------------------------------------------
// Problem constants
// ---------------------------------------------------------------------------
#define BATCH 32
#define SEQ   512
#define DMODEL 512
#define DTIME  256
#define NHEAD  8
#define HD     64
#define VD     32
#define DFF    2048
#define NROWS  (BATCH * SEQ)      // 16384
#define DCAT   (DMODEL + DTIME)   // 768
#define MTN    16

// ---------------------------------------------------------------------------
// Scratch (device globals; no runtime allocation)
// ---------------------------------------------------------------------------
__device__ float g_tmp [ (size_t)NROWS * DMODEL ];
__device__ float g_xtok[ (size_t)NROWS * DMODEL ];
__device__ float g_xtim[ (size_t)NROWS * DTIME  ];
__device__ float g_qkv [ (size_t)NROWS * 3 * DMODEL ];
__device__ float g_attn[ (size_t)NROWS * DMODEL ];
__device__ float g_diag[ (size_t)NROWS * NHEAD  ];
__device__ float g_xc  [ (size_t)NROWS * DCAT   ];
__device__ float g_ff1 [ (size_t)NROWS * DFF    ];
__device__ float g_ff2 [ (size_t)NROWS * DCAT   ];
__device__ float g_pool[ (size_t)BATCH * (SEQ/MTN) * DCAT ];
__device__ float g_fin [ (size_t)BATCH * (SEQ/MTN) * DTIME ];

// ---------------------------------------------------------------------------
// Helpers
// ---------------------------------------------------------------------------
__device__ __forceinline__ float f2tf(float x) {
    unsigned r;
    asm("cvt.rna.tf32.f32 %0, %1;" : "=r"(r) : "f"(x));
    return __uint_as_float(r);
}

__device__ __forceinline__ int perm8(int j) {   // k-pair permutation within 8
    return (j < 4) ? 2 * j : 2 * (j - 4) + 1;
}

__device__ __forceinline__ void mma_tf32(float* d, const float* a, const float* b) {
    asm volatile(
        "mma.sync.aligned.m16n8k8.row.col.f32.tf32.tf32.f32 "
        "{%0,%1,%2,%3},{%4,%5,%6,%7},{%8,%9},{%0,%1,%2,%3};\n"
        : "+f"(d[0]), "+f"(d[1]), "+f"(d[2]), "+f"(d[3])
        : "r"(__float_as_uint(a[0])), "r"(__float_as_uint(a[1])),
          "r"(__float_as_uint(a[2])), "r"(__float_as_uint(a[3])),
          "r"(__float_as_uint(b[0])), "r"(__float_as_uint(b[1])));
}

// ---------------------------------------------------------------------------
// Warp-per-row LayerNorm (optionally *(1+diag_head), optionally +res)
// blockDim 256 (8 rows/block). D in {256, 512}.
// ---------------------------------------------------------------------------
__global__ __launch_bounds__(256) void ln_warp(
    const float* __restrict__ in, int istride,
    const float* __restrict__ res, int rstride,
    const float* __restrict__ diag,
    const float* __restrict__ g, const float* __restrict__ b,
    float* __restrict__ out, int ostride, int D)
{
    const int lane = threadIdx.x & 31;
    const int row  = blockIdx.x * 8 + (threadIdx.x >> 5);
    const float* ip = in + (size_t)row * istride;
    const int nv = D >> 7;              // float4 per lane (2 or 4)

    float v[16];
    float sum = 0.f;
#pragma unroll
    for (int w = 0; w < 4; ++w) {
        if (w < nv) {
            int c = w * 128 + lane * 4;
            float4 t = *(const float4*)(ip + c);
            if (diag) {
                float dm = 1.f + diag[(size_t)row * NHEAD + (c >> 5)];
                t.x *= dm; t.y *= dm; t.z *= dm; t.w *= dm;
            }
            if (res) {
                const float* rp = res + (size_t)row * rstride + c;
                t.x += rp[0]; t.y += rp[1]; t.z += rp[2]; t.w += rp[3];
            }
            v[w*4+0] = t.x; v[w*4+1] = t.y; v[w*4+2] = t.z; v[w*4+3] = t.w;
            sum += t.x + t.y + t.z + t.w;
        }
    }
#pragma unroll
    for (int o = 16; o; o >>= 1) sum += __shfl_xor_sync(0xffffffffu, sum, o);
    const float mean = sum / D;

    float vs = 0.f;
#pragma unroll
    for (int w = 0; w < 4; ++w)
        if (w < nv)
#pragma unroll
            for (int q = 0; q < 4; ++q) {
                float d2 = v[w*4+q] - mean;
                vs += d2 * d2;
            }
#pragma unroll
    for (int o = 16; o; o >>= 1) vs += __shfl_xor_sync(0xffffffffu, vs, o);
    const float rstd = rsqrtf(vs / D + 1e-5f);

#pragma unroll
    for (int w = 0; w < 4; ++w) {
        if (w < nv) {
            int c = w * 128 + lane * 4;
            float4 o4;
            o4.x = (v[w*4+0] - mean) * rstd * g[c+0] + b[c+0];
            o4.y = (v[w*4+1] - mean) * rstd * g[c+1] + b[c+1];
            o4.z = (v[w*4+2] - mean) * rstd * g[c+2] + b[c+2];
            o4.w = (v[w*4+3] - mean) * rstd * g[c+3] + b[c+3];
            *(float4*)(out + (size_t)row * ostride + c) = o4;
        }
    }
}

// ---------------------------------------------------------------------------
// tf32 tensor-core NT GEMM (unchanged from R2; known-good)
// ---------------------------------------------------------------------------
__global__ __launch_bounds__(256) void gemm_tf32(
    const float* __restrict__ A, const float* __restrict__ W,
    const float* __restrict__ bias, float* __restrict__ C,
    int N, int M, int K, int act)
{
    __shared__ float As[2][128][24];
    __shared__ float Bs[2][128][24];

    const int tid  = threadIdx.x;
    const int lane = tid & 31;
    const int warp = tid >> 5;
    const int wm = (warp & 1) * 64;
    const int wn = (warp >> 1) * 32;
    const int r4 = lane >> 2;
    const int c2 = (lane & 3) * 2;

    const int row0 = blockIdx.y * 128;
    const int col0 = blockIdx.x * 128;

    const int lrow = tid >> 1;
    const int lk   = (tid & 1) * 8;

    const float* Ap = A + (size_t)(row0 + lrow) * K + lk;
    const float* Wp = W + (size_t)(col0 + lrow) * K + lk;

    float acc[4][4][4];
#pragma unroll
    for (int i = 0; i < 4; ++i)
#pragma unroll
        for (int j = 0; j < 4; ++j)
#pragma unroll
            for (int q = 0; q < 4; ++q) acc[i][j][q] = 0.f;

    float4 ra0, ra1, rb0, rb1;

#define LOAD_TILE(kt)                                            \
    do {                                                         \
        const int k0_ = (kt) * 16;                               \
        ra0 = *(const float4*)(Ap + k0_);                        \
        ra1 = *(const float4*)(Ap + k0_ + 4);                    \
        rb0 = *(const float4*)(Wp + k0_);                        \
        rb1 = *(const float4*)(Wp + k0_ + 4);                    \
    } while (0)

#define STORE_TILE(bb)                                                        \
    do {                                                                      \
        float* da = &As[bb][lrow][lk];                                        \
        float* db = &Bs[bb][lrow][lk];                                        \
        ((float2*)da)[0] = make_float2(f2tf(ra0.x), f2tf(ra1.x));             \
        ((float2*)da)[1] = make_float2(f2tf(ra0.y), f2tf(ra1.y));             \
        ((float2*)da)[2] = make_float2(f2tf(ra0.z), f2tf(ra1.z));             \
        ((float2*)da)[3] = make_float2(f2tf(ra0.w), f2tf(ra1.w));             \
        ((float2*)db)[0] = make_float2(f2tf(rb0.x), f2tf(rb1.x));             \
        ((float2*)db)[1] = make_float2(f2tf(rb0.y), f2tf(rb1.y));             \
        ((float2*)db)[2] = make_float2(f2tf(rb0.z), f2tf(rb1.z));             \
        ((float2*)db)[3] = make_float2(f2tf(rb0.w), f2tf(rb1.w));             \
    } while (0)

    const int NT = K >> 4;
    LOAD_TILE(0);
    STORE_TILE(0);
    __syncthreads();

    for (int kt = 0; kt < NT; ++kt) {
        const int buf = kt & 1;
        if (kt + 1 < NT) LOAD_TILE(kt + 1);

#pragma unroll
        for (int s = 0; s < 2; ++s) {
            const int ko = s * 8;
            float a[4][4], b[4][2];
#pragma unroll
            for (int mt = 0; mt < 4; ++mt) {
                float2 t0 = *(const float2*)&As[buf][wm + mt * 16 + r4][ko + c2];
                float2 t1 = *(const float2*)&As[buf][wm + mt * 16 + 8 + r4][ko + c2];
                a[mt][0] = t0.x; a[mt][1] = t1.x; a[mt][2] = t0.y; a[mt][3] = t1.y;
            }
#pragma unroll
            for (int nt = 0; nt < 4; ++nt) {
                float2 tb = *(const float2*)&Bs[buf][wn + nt * 8 + r4][ko + c2];
                b[nt][0] = tb.x; b[nt][1] = tb.y;
            }
#pragma unroll
            for (int mt = 0; mt < 4; ++mt)
#pragma unroll
                for (int nt = 0; nt < 4; ++nt)
                    mma_tf32(acc[mt][nt], a[mt], b[nt]);
        }

        if (kt + 1 < NT) {
            STORE_TILE(buf ^ 1);
            __syncthreads();
        }
    }
#undef LOAD_TILE
#undef STORE_TILE

#pragma unroll
    for (int mt = 0; mt < 4; ++mt) {
        const int row = row0 + wm + mt * 16 + r4;
#pragma unroll
        for (int nt = 0; nt < 4; ++nt) {
            const int col = col0 + wn + nt * 8 + c2;
            const float b0 = bias[col], b1 = bias[col + 1];
            float v[4];
            v[0] = acc[mt][nt][0] + b0;
            v[1] = acc[mt][nt][1] + b1;
            v[2] = acc[mt][nt][2] + b0;
            v[3] = acc[mt][nt][3] + b1;
            if (act == 1) {
#pragma unroll
                for (int q = 0; q < 4; ++q) v[q] = fmaxf(v[q], 0.f);
            } else if (act == 2) {
#pragma unroll
                for (int q = 0; q < 4; ++q)
                    v[q] = 0.5f * v[q] * (1.f + erff(v[q] * 0.70710678118654752f));
            }
            *(float2*)&C[(size_t)row * M + col]       = make_float2(v[0], v[1]);
            *(float2*)&C[(size_t)(row + 8) * M + col] = make_float2(v[2], v[3]);
        }
    }
}

// ---------------------------------------------------------------------------
// Tensor-core flash attention (split-tf32 QK^T, tf32 PV) + diag extraction.
// grid (SEQ/64, NHEAD, BATCH), 128 threads (4 warps, warp = 16 q-rows).
// Dynamic smem: Qh, Ql, Kh, Kl, Ps  (each 64 x 72 floats) = 90 KB.
// V^T reuses Kh after S is computed.
// ---------------------------------------------------------------------------
#define ATT_STRIDE 72
#define ATT_BUF (64 * ATT_STRIDE)

__global__ __launch_bounds__(128) void attn_tc(
    const float* __restrict__ qkv,
    float* __restrict__ attn_out,
    float* __restrict__ diag_out)
{
    extern __shared__ float sm[];
    float* Qh = sm;
    float* Ql = Qh + ATT_BUF;
    float* Kh = Ql + ATT_BUF;
    float* Kl = Kh + ATT_BUF;
    float* Ps = Kl + ATT_BUF;

    const int qt = blockIdx.x, h = blockIdx.y, b = blockIdx.z;
    const int tid  = threadIdx.x;
    const int lane = tid & 31, warp = tid >> 5;
    const int r4 = lane >> 2;             // row within m16 half / n within n8
    const int c2 = (lane & 3) * 2;        // permuted k-pair offset
    const int wr = warp * 16;             // warp q-row base within tile
    const size_t rowbase = (size_t)b * SEQ;
    const int q0 = qt * 64;
    const int qoff = h * HD;

    // ---- load Q (scaled by 1/sqrt(64), split hi/lo, d-pair-permuted) ----
    for (int i = tid; i < 1024; i += 128) {
        int r = i >> 4, c4 = (i & 15) << 2;
        float4 v = *(const float4*)(qkv + (rowbase + q0 + r) * 1536 + qoff + c4);
        float vv[4] = {v.x, v.y, v.z, v.w};
#pragma unroll
        for (int j = 0; j < 4; ++j) {
            int d = c4 + j;
            int col = (d & ~7) + perm8(d & 7);
            float x  = vv[j] * 0.125f;
            float hi = f2tf(x);
            Qh[r * ATT_STRIDE + col] = hi;
            Ql[r * ATT_STRIDE + col] = f2tf(x - hi);
        }
    }

    float oacc[8][4];
#pragma unroll
    for (int nf = 0; nf < 8; ++nf)
#pragma unroll
        for (int q = 0; q < 4; ++q) oacc[nf][q] = 0.f;

    float mA = -1e30f, mB = -1e30f, lA = 0.f, lB = 0.f, duA = 0.f, duB = 0.f;

    const int p0 = perm8(c2);         // P store positions for the 2 slots
    const int p1 = perm8(c2 + 1);

    for (int kt = 0; kt < 8; ++kt) {
        const int kb = kt * 64;
        __syncthreads();               // prev PV done reading Kh / K load of Kl

        // ---- load K tile (split hi/lo) ----
        for (int i = tid; i < 1024; i += 128) {
            int r = i >> 4, c4 = (i & 15) << 2;
            float4 v = *(const float4*)(qkv + (rowbase + kb + r) * 1536 + 512 + qoff + c4);
            float vv[4] = {v.x, v.y, v.z, v.w};
#pragma unroll
            for (int j = 0; j < 4; ++j) {
                int d = c4 + j;
                int col = (d & ~7) + perm8(d & 7);
                float hi = f2tf(vv[j]);
                Kh[r * ATT_STRIDE + col] = hi;
                Kl[r * ATT_STRIDE + col] = f2tf(vv[j] - hi);
            }
        }
        __syncthreads();

        // ---- S = Q K^T  (3-term split tf32) ----
        float sacc[8][4];
#pragma unroll
        for (int nf = 0; nf < 8; ++nf)
#pragma unroll
            for (int q = 0; q < 4; ++q) sacc[nf][q] = 0.f;

#pragma unroll
        for (int kg = 0; kg < 8; ++kg) {
            const int ko = kg * 8 + c2;
            float2 qh0 = *(const float2*)&Qh[(wr + r4) * ATT_STRIDE + ko];
            float2 qh1 = *(const float2*)&Qh[(wr + 8 + r4) * ATT_STRIDE + ko];
            float2 ql0 = *(const float2*)&Ql[(wr + r4) * ATT_STRIDE + ko];
            float2 ql1 = *(const float2*)&Ql[(wr + 8 + r4) * ATT_STRIDE + ko];
            float ah[4] = {qh0.x, qh1.x, qh0.y, qh1.y};
            float al[4] = {ql0.x, ql1.x, ql0.y, ql1.y};
#pragma unroll
            for (int nf = 0; nf < 8; ++nf) {
                float2 bh = *(const float2*)&Kh[(nf * 8 + r4) * ATT_STRIDE + ko];
                float2 bl = *(const float2*)&Kl[(nf * 8 + r4) * ATT_STRIDE + ko];
                float bhv[2] = {bh.x, bh.y};
                float blv[2] = {bl.x, bl.y};
                mma_tf32(sacc[nf], ah, bhv);
                mma_tf32(sacc[nf], ah, blv);
                mma_tf32(sacc[nf], al, bhv);
            }
        }

        // ---- online softmax (rows rA = wr+r4, rB = rA+8) ----
        float mxA = -1e30f, mxB = -1e30f;
#pragma unroll
        for (int nf = 0; nf < 8; ++nf) {
            mxA = fmaxf(mxA, fmaxf(sacc[nf][0], sacc[nf][1]));
            mxB = fmaxf(mxB, fmaxf(sacc[nf][2], sacc[nf][3]));
        }
#pragma unroll
        for (int o = 1; o <= 2; o <<= 1) {
            mxA = fmaxf(mxA, __shfl_xor_sync(0xffffffffu, mxA, o));
            mxB = fmaxf(mxB, __shfl_xor_sync(0xffffffffu, mxB, o));
        }
        const float mnA = fmaxf(mA, mxA), mnB = fmaxf(mB, mxB);
        const float cfA = expf(mA - mnA), cfB = expf(mB - mnB);
        float sA = 0.f, sB = 0.f;
#pragma unroll
        for (int nf = 0; nf < 8; ++nf) {
            sacc[nf][0] = expf(sacc[nf][0] - mnA);
            sacc[nf][1] = expf(sacc[nf][1] - mnA);
            sacc[nf][2] = expf(sacc[nf][2] - mnB);
            sacc[nf][3] = expf(sacc[nf][3] - mnB);
            sA += sacc[nf][0] + sacc[nf][1];
            sB += sacc[nf][2] + sacc[nf][3];
        }
#pragma unroll
        for (int o = 1; o <= 2; o <<= 1) {
            sA += __shfl_xor_sync(0xffffffffu, sA, o);
            sB += __shfl_xor_sync(0xffffffffu, sB, o);
        }
        lA = lA * cfA + sA;
        lB = lB * cfB + sB;
        duA *= cfA; duB *= cfB;
#pragma unroll
        for (int nf = 0; nf < 8; ++nf) {
            oacc[nf][0] *= cfA; oacc[nf][1] *= cfA;
            oacc[nf][2] *= cfB; oacc[nf][3] *= cfB;
        }
        mA = mnA; mB = mnB;

        // ---- diag extraction ----
        {
            const int gqA = q0 + wr + r4;
            const int jA = gqA - kb;
            if (jA >= 0 && jA < 64 && ((jA & 7) >> 1) == (lane & 3))
                duA += sacc[jA >> 3][jA & 1];
            const int jB = gqA + 8 - kb;
            if (jB >= 0 && jB < 64 && ((jB & 7) >> 1) == (lane & 3))
                duB += sacc[jB >> 3][2 + (jB & 1)];
        }

        // ---- store P (tf32, kv-pair-permuted) ----
#pragma unroll
        for (int nf = 0; nf < 8; ++nf) {
            float* prA = &Ps[(wr + r4) * ATT_STRIDE + nf * 8];
            float* prB = &Ps[(wr + 8 + r4) * ATT_STRIDE + nf * 8];
            prA[p0] = f2tf(sacc[nf][0]);
            prA[p1] = f2tf(sacc[nf][1]);
            prB[p0] = f2tf(sacc[nf][2]);
            prB[p1] = f2tf(sacc[nf][3]);
        }
        __syncthreads();               // S/P done; Kh free for V^T

        // ---- load V^T into Kh (kv-pair-permuted columns) ----
        for (int i = tid; i < 1024; i += 128) {
            int r = i & 63, c4 = (i >> 6) << 2;
            float4 v = *(const float4*)(qkv + (rowbase + kb + r) * 1536 + 1024 + qoff + c4);
            int pc = (r & ~7) + perm8(r & 7);
            Kh[(c4 + 0) * ATT_STRIDE + pc] = f2tf(v.x);
            Kh[(c4 + 1) * ATT_STRIDE + pc] = f2tf(v.y);
            Kh[(c4 + 2) * ATT_STRIDE + pc] = f2tf(v.z);
            Kh[(c4 + 3) * ATT_STRIDE + pc] = f2tf(v.w);
        }
        __syncthreads();

        // ---- O += P V ----
#pragma unroll
        for (int kg = 0; kg < 8; ++kg) {
            const int ko = kg * 8 + c2;
            float2 pa0 = *(const float2*)&Ps[(wr + r4) * ATT_STRIDE + ko];
            float2 pa1 = *(const float2*)&Ps[(wr + 8 + r4) * ATT_STRIDE + ko];
            float a[4] = {pa0.x, pa1.x, pa0.y, pa1.y};
#pragma unroll
            for (int nf = 0; nf < 8; ++nf) {
                float2 vb = *(const float2*)&Kh[(nf * 8 + r4) * ATT_STRIDE + ko];
                float bv[2] = {vb.x, vb.y};
                mma_tf32(oacc[nf], a, bv);
            }
        }
    }

    // ---- epilogue ----
    const float ivA = 1.f / lA, ivB = 1.f / lB;
    const size_t rA = rowbase + q0 + wr + r4;
    const size_t rB = rA + 8;
#pragma unroll
    for (int nf = 0; nf < 8; ++nf) {
        const int col = qoff + nf * 8 + c2;
        *(float2*)&attn_out[rA * DMODEL + col] =
            make_float2(oacc[nf][0] * ivA, oacc[nf][1] * ivA);
        *(float2*)&attn_out[rB * DMODEL + col] =
            make_float2(oacc[nf][2] * ivB, oacc[nf][3] * ivB);
    }
    float dA = duA * ivA, dB = duB * ivB;
#pragma unroll
    for (int o = 1; o <= 2; o <<= 1) {
        dA += __shfl_xor_sync(0xffffffffu, dA, o);
        dB += __shfl_xor_sync(0xffffffffu, dB, o);
    }
    if ((lane & 3) == 0) {
        diag_out[rA * NHEAD + h] = dA;
        diag_out[rB * NHEAD + h] = dB;
    }
}

// ---------------------------------------------------------------------------
// MaxPool over seq (k=stride=16) producing concatenated [B,32,768]
// ---------------------------------------------------------------------------
__global__ __launch_bounds__(256) void pool_kernel(
    const float* __restrict__ xtok, const float* __restrict__ xtim,
    float* __restrict__ pool)
{
    const int bidx = blockIdx.x;
    const int b = bidx >> 5, ch = bidx & 31;
    const size_t r0 = (size_t)b * SEQ + ch * MTN;
    for (int c = threadIdx.x; c < DCAT; c += 256) {
        float mx = -1e30f;
        if (c < DMODEL) {
            const float* p = xtok + r0 * DMODEL + c;
#pragma unroll
            for (int t = 0; t < MTN; ++t) mx = fmaxf(mx, p[(size_t)t * DMODEL]);
        } else {
            const float* p = xtim + r0 * DTIME + (c - DMODEL);
#pragma unroll
            for (int t = 0; t < MTN; ++t) mx = fmaxf(mx, p[(size_t)t * DTIME]);
        }
        pool[(size_t)bidx * DCAT + c] = mx;
    }
}

// ---------------------------------------------------------------------------
// Host driver
// ---------------------------------------------------------------------------
#define ATT_SMEM (5 * ATT_BUF * (int)sizeof(float))   // 92160 B

extern "C" void kernel_launch(void* const* d_in, const int* in_sizes, int n_in,
                              void* d_out, int out_size)
{
    const float* src_token = (const float*)d_in[0];
    const float* src_time  = (const float*)d_in[1];
    const float* norm0_g   = (const float*)d_in[2];
    const float* norm0_b   = (const float*)d_in[3];
    const float* in_w      = (const float*)d_in[4];
    const float* in_b      = (const float*)d_in[5];
    const float* qkv_w     = (const float*)d_in[6];
    const float* qkv_b     = (const float*)d_in[7];
    const float* ao_w      = (const float*)d_in[8];
    const float* ao_b      = (const float*)d_in[9];
    const float* lin1_w    = (const float*)d_in[10];
    const float* lin1_b    = (const float*)d_in[11];
    const float* lin2_w    = (const float*)d_in[12];
    const float* lin2_b    = (const float*)d_in[13];
    const float* n1_g = (const float*)d_in[14];
    const float* n1_b = (const float*)d_in[15];
    const float* n2_g = (const float*)d_in[16];
    const float* n2_b = (const float*)d_in[17];
    const float* n3_g = (const float*)d_in[18];
    const float* n3_b = (const float*)d_in[19];
    const float* n4_g = (const float*)d_in[20];
    const float* n4_b = (const float*)d_in[21];
    const float* out_w = (const float*)d_in[22];
    const float* out_b = (const float*)d_in[23];
    const float* ln_g  = (const float*)d_in[24];
    const float* ln_b  = (const float*)d_in[25];
    float* outp = (float*)d_out;

    static int smem_set = 0;
    if (!smem_set) {
        cudaFuncSetAttribute(attn_tc, cudaFuncAttributeMaxDynamicSharedMemorySize,
                             ATT_SMEM);
        smem_set = 1;
    }

    float *tmp, *xtok, *xtim, *qkv, *attn, *diag, *xc, *ff1, *ff2, *pool, *fin;
    cudaGetSymbolAddress((void**)&tmp,  g_tmp);
    cudaGetSymbolAddress((void**)&xtok, g_xtok);
    cudaGetSymbolAddress((void**)&xtim, g_xtim);
    cudaGetSymbolAddress((void**)&qkv,  g_qkv);
    cudaGetSymbolAddress((void**)&attn, g_attn);
    cudaGetSymbolAddress((void**)&diag, g_diag);
    cudaGetSymbolAddress((void**)&xc,   g_xc);
    cudaGetSymbolAddress((void**)&ff1,  g_ff1);
    cudaGetSymbolAddress((void**)&ff2,  g_ff2);
    cudaGetSymbolAddress((void**)&pool, g_pool);
    cudaGetSymbolAddress((void**)&fin,  g_fin);

    const float* xtok_in = src_token;
    const float* xtim_in = src_time;

    for (int i = 0; i < 2; ++i) {
        const float* n0g = norm0_g + i * 512;
        const float* n0b = norm0_b + i * 512;
        const float* iw  = in_w  + (size_t)i * 512 * 512;
        const float* ib  = in_b  + i * 512;
        const float* qw  = qkv_w + (size_t)i * 1536 * 512;
        const float* qb  = qkv_b + i * 1536;
        const float* aw  = ao_w  + (size_t)i * 512 * 512;
        const float* ab  = ao_b  + i * 512;
        const float* l1w = lin1_w + (size_t)i * 2048 * 768;
        const float* l1b = lin1_b + i * 2048;
        const float* l2w = lin2_w + (size_t)i * 768 * 2048;
        const float* l2b = lin2_b + i * 768;

        ln_warp<<<NROWS / 8, 256>>>(xtok_in, 512, nullptr, 0, nullptr,
                                    n0g, n0b, tmp, 512, 512);
        gemm_tf32<<<dim3(4, 128), 256>>>(tmp, iw, ib, xtok, NROWS, 512, 512, 0);
        gemm_tf32<<<dim3(12, 128), 256>>>(xtok, qw, qb, qkv, NROWS, 1536, 512, 0);
        attn_tc<<<dim3(8, 8, 32), 128, ATT_SMEM>>>(qkv, attn, diag);
        gemm_tf32<<<dim3(4, 128), 256>>>(attn, aw, ab, tmp, NROWS, 512, 512, 0);
        ln_warp<<<NROWS / 8, 256>>>(tmp, 512, xtok, 512, nullptr,
                                    n1_g + i * 512, n1_b + i * 512, xc, 768, 512);
        ln_warp<<<NROWS / 8, 256>>>(xtim_in, 256, nullptr, 0, diag,
                                    n2_g + i * 256, n2_b + i * 256, xc + 512, 768, 256);
        gemm_tf32<<<dim3(16, 128), 256>>>(xc, l1w, l1b, ff1, NROWS, 2048, 768, 1);
        gemm_tf32<<<dim3(6, 128), 256>>>(ff1, l2w, l2b, ff2, NROWS, 768, 2048, 0);
        ln_warp<<<NROWS / 8, 256>>>(ff2, 768, xc, 768, nullptr,
                                    n3_g + i * 512, n3_b + i * 512, xtok, 512, 512);
        ln_warp<<<NROWS / 8, 256>>>(ff2 + 512, 768, xc + 512, 768, nullptr,
                                    n4_g + i * 256, n4_b + i * 256, xtim, 256, 256);

        xtok_in = xtok;
        xtim_in = xtim;
    }

    pool_kernel<<<1024, 256>>>(xtok, xtim, pool);
    gemm_tf32<<<dim3(2, 8), 256>>>(pool, out_w, out_b, fin, 1024, 256, 768, 2);
    ln_warp<<<128, 256>>>(fin, 256, nullptr, 0, nullptr, ln_g, ln_b,
                          outp, 256, 256);
}